// round 12
// baseline (speedup 1.0000x reference)
#include <cuda_runtime.h>

// Single self-contained kernel. Each CTA's warp 0 computes the two real 3x3
// bilinear forms M (observables Z0, Z1) cooperatively from q_weights into
// shared memory, while the other warps' noise loads are already in flight
// (issued before the barrier). Then all threads evaluate 4 samples each:
//   z_k = (1, X0, Y0) * M_k * (1, X1, Y1)^T,  X = cos(pi*n), Y = sin(pi*n).

__device__ __forceinline__ float bil(const float* m,
                                     float X0, float Y0, float X1, float Y1) {
    float d0 = fmaf(m[2], Y1, fmaf(m[1], X1, m[0]));
    float d1 = fmaf(m[5], Y1, fmaf(m[4], X1, m[3]));
    float d2 = fmaf(m[8], Y1, fmaf(m[7], X1, m[6]));
    return fmaf(Y0, d2, fmaf(X0, d1, d0));
}

__global__ void __launch_bounds__(512) qcirc_kernel(
    const float4* __restrict__ noise, float4* __restrict__ out,
    const float* __restrict__ qw, int t)
{
    __shared__ float sc[12], ss[12];        // sincos of the 12 half-angles
    __shared__ float sgr[16], sgi[16];      // gate entries (l,w,i,j)
    __shared__ float sWr[16], sWi[16];      // final W (row r, col m)
    __shared__ float sReA[32];              // Re(W^H S W), 2 obs x 16
    __shared__ __align__(16) float sM[20];  // output bilinear forms

    const unsigned FULL = 0xFFFFFFFFu;
    int tid = threadIdx.x;

    // ---- Issue the stream loads FIRST: in flight during prep --------------
    int idx = blockIdx.x * blockDim.x + tid;
    bool valid = (idx < t);
    float4 a = make_float4(0.f, 0.f, 0.f, 0.f);
    float4 b = a;
    if (valid) {
        a = noise[idx];
        b = noise[idx + t];
    }

    // ---- Warp 0: cooperative prep (~500 cyc), overlapped with loads -------
    if (tid < 32) {
        int lane = tid;

        // Stage 1: 12 sincos in parallel
        if (lane < 12) {
            int l = lane / 6, rem = lane % 6, w = rem / 3, k = rem % 3;
            float phi = qw[l * 6 + w * 3 + 0];
            float th  = qw[l * 6 + w * 3 + 1];
            float om  = qw[l * 6 + w * 3 + 2];
            float ang = (k == 0) ? 0.5f * th
                      : (k == 1) ? 0.5f * (phi + om)
                                 : 0.5f * (phi - om);
            float s, c;
            __sincosf(ang, &s, &c);
            sc[lane] = c; ss[lane] = s;
        }
        __syncwarp(FULL);

        // Stage 2: 16 gate entries in parallel.
        // Rot = RZ(om) RY(th) RZ(phi):
        //  (0,0)=( ct*ca, -ct*sa)  (0,1)=(-st*cb, -st*sb)
        //  (1,0)=( st*cb, -st*sb)  (1,1)=( ct*ca,  ct*sa)
        if (lane < 16) {
            int l = lane >> 3, w = (lane >> 2) & 1, i = (lane >> 1) & 1, j = lane & 1;
            int base = l * 6 + w * 3;
            float ct = sc[base + 0], st = ss[base + 0];
            float ca = sc[base + 1], sa = ss[base + 1];
            float cb = sc[base + 2], sb = ss[base + 2];
            float re = (i == j) ? ct * ca : ((i == 0) ? -st * cb : st * cb);
            float im = (i == 0) ? ((j == 0) ? -ct * sa : -st * sb)
                                : ((j == 0) ? -st * sb :  ct * sa);
            sgr[lane] = re; sgi[lane] = im;
        }
        __syncwarp(FULL);

        // Stage 3: W evolution, one complex entry per lane.
        // q = r*4 + m, r = basis row (i*2+j), m = column. Lanes 16-31 mirror.
        int q = lane & 15;
        int r = q >> 2, m = q & 3;
        int i = r >> 1, j = r & 1;
        // W init = D = diag(1, -i, -i, -1)
        float wr = (q == 0) ? 1.f : ((q == 15) ? -1.f : 0.f);
        float wi = (q == 5 || q == 10) ? -1.f : 0.f;

        #pragma unroll
        for (int l = 0; l < 2; l++) {
            // Gate on qubit 0: new(i,j) = g0[i][0]*W(0,j) + g0[i][1]*W(1,j)
            {
                float ar = __shfl_sync(FULL, wr, j * 4 + m);
                float ai = __shfl_sync(FULL, wi, j * 4 + m);
                float br = __shfl_sync(FULL, wr, (2 + j) * 4 + m);
                float bi = __shfl_sync(FULL, wi, (2 + j) * 4 + m);
                int c0 = (l * 2 + 0) * 4 + i * 2;
                float g0r = sgr[c0],     g0i = sgi[c0];
                float g1r = sgr[c0 + 1], g1i = sgi[c0 + 1];
                wr = g0r * ar - g0i * ai + g1r * br - g1i * bi;
                wi = g0r * ai + g0i * ar + g1r * bi + g1i * br;
            }
            // Gate on qubit 1: new(i,j) = g1[j][0]*W(i,0) + g1[j][1]*W(i,1)
            {
                float ar = __shfl_sync(FULL, wr, (2 * i) * 4 + m);
                float ai = __shfl_sync(FULL, wi, (2 * i) * 4 + m);
                float br = __shfl_sync(FULL, wr, (2 * i + 1) * 4 + m);
                float bi = __shfl_sync(FULL, wi, (2 * i + 1) * 4 + m);
                int c0 = (l * 2 + 1) * 4 + j * 2;
                float g0r = sgr[c0],     g0i = sgi[c0];
                float g1r = sgr[c0 + 1], g1i = sgi[c0 + 1];
                wr = g0r * ar - g0i * ai + g1r * br - g1i * bi;
                wi = g0r * ai + g0i * ar + g1r * bi + g1i * br;
            }
            // Fused CNOT(0->1) then CNOT(1->0): new(i,j) = old(i^j, i)
            {
                int sp = ((i ^ j) * 2 + i) * 4 + m;
                float nwr = __shfl_sync(FULL, wr, sp);
                float nwi = __shfl_sync(FULL, wi, sp);
                wr = nwr; wi = nwi;
            }
        }
        if (lane < 16) { sWr[q] = wr; sWi[q] = wi; }
        __syncwarp(FULL);

        // Stage 4: ReA[j][m] = Re((W^H S W))[j][m], one per lane
        {
            int obs = lane >> 4, jj = (lane >> 2) & 3, mm = lane & 3;
            float acc = 0.f;
            #pragma unroll
            for (int k = 0; k < 4; k++) {
                float sk = (obs == 0) ? ((k < 2) ? 1.f : -1.f)
                                      : ((k & 1) ? -1.f : 1.f);
                acc += sk * (sWr[k * 4 + jj] * sWr[k * 4 + mm]
                           + sWi[k * 4 + jj] * sWi[k * 4 + mm]);
            }
            sReA[lane] = acc;
        }
        __syncwarp(FULL);

        // Stage 5: project onto (1,X,Y) x (1,X,Y), one M entry per lane.
        // Qu sparsity: index e has two (a,b,sign) pairs:
        //  e=0: (0,0,+),(1,1,+)  e=1: (0,0,+),(1,1,-)  e=2: (0,1,+),(1,0,+)
        if (lane < 20) {
            if (lane < 18) {
                const int   A0[3] = {0, 0, 0}, B0[3] = {0, 0, 1};
                const int   A1[3] = {1, 1, 1}, B1[3] = {1, 1, 0};
                const float S1[3] = {1.f, -1.f, 1.f};
                int obs = lane / 9, e = lane % 9, al = e / 3, be = e % 3;
                const float* Rbase = sReA + obs * 16;
                float acc = 0.f;
                #pragma unroll
                for (int p = 0; p < 2; p++) {
                    int ap = p ? A1[al] : A0[al];
                    int bp = p ? B1[al] : B0[al];
                    float sp = p ? S1[al] : 1.f;
                    #pragma unroll
                    for (int qq = 0; qq < 2; qq++) {
                        int aq = qq ? A1[be] : A0[be];
                        int bq = qq ? B1[be] : B0[be];
                        float sq = qq ? S1[be] : 1.f;
                        acc += sp * sq * Rbase[(2 * ap + aq) * 4 + (2 * bp + bq)];
                    }
                }
                sM[lane] = 0.25f * acc;
            } else {
                sM[lane] = 0.f;
            }
        }
    }
    __syncthreads();

    // ---- Hot path: loads already landed; 5x LDS.128 broadcast + math ------
    if (!valid) return;

    float M[20];
    const float4* sp4 = reinterpret_cast<const float4*>(sM);
    #pragma unroll
    for (int k = 0; k < 5; k++) {
        float4 v = sp4[k];
        M[4 * k + 0] = v.x; M[4 * k + 1] = v.y;
        M[4 * k + 2] = v.z; M[4 * k + 3] = v.w;
    }

    const float PI = 3.14159265358979323846f;
    float Xa, Ya, Xb, Yb, Xc, Yc, Xd, Yd;
    float4 ra, rb;

    __sincosf(a.x * PI, &Ya, &Xa);
    __sincosf(a.y * PI, &Yb, &Xb);
    __sincosf(a.z * PI, &Yc, &Xc);
    __sincosf(a.w * PI, &Yd, &Xd);
    ra.x = bil(M + 0, Xa, Ya, Xb, Yb);
    ra.y = bil(M + 9, Xa, Ya, Xb, Yb);
    ra.z = bil(M + 0, Xc, Yc, Xd, Yd);
    ra.w = bil(M + 9, Xc, Yc, Xd, Yd);

    __sincosf(b.x * PI, &Ya, &Xa);
    __sincosf(b.y * PI, &Yb, &Xb);
    __sincosf(b.z * PI, &Yc, &Xc);
    __sincosf(b.w * PI, &Yd, &Xd);
    rb.x = bil(M + 0, Xa, Ya, Xb, Yb);
    rb.y = bil(M + 9, Xa, Ya, Xb, Yb);
    rb.z = bil(M + 0, Xc, Yc, Xd, Yd);
    rb.w = bil(M + 9, Xc, Yc, Xd, Yd);

    out[idx] = ra;
    out[idx + t] = rb;
}

extern "C" void kernel_launch(void* const* d_in, const int* in_sizes, int n_in,
                              void* d_out, int out_size) {
    const float* noise = (const float*)d_in[0];     // [B, 2] f32
    const float* qw    = (const float*)d_in[1];     // [2, 2, 3] f32

    int n4 = in_sizes[0] / 4;   // float4 count
    int t = n4 / 2;             // threads; each handles float4 idx and idx+t
    int threads = 512;          // fewer CTAs -> fewer prep instances per SM
    int blocks = (t + threads - 1) / threads;
    qcirc_kernel<<<blocks, threads>>>(
        (const float4*)noise, (float4*)d_out, qw, t);
}

// round 14
// speedup vs baseline: 1.1257x; 1.1257x over previous
#include <cuda_runtime.h>

// Single self-contained kernel. Each CTA's warp 0 computes the two real 3x3
// bilinear forms M (observables Z0, Z1) cooperatively from q_weights into
// shared memory (~500 cycles, no global state, no inter-block sync), then
// all threads evaluate 4 samples each:
//   z_k = (1, X0, Y0) * M_k * (1, X1, Y1)^T,  X = cos(pi*n), Y = sin(pi*n).
// __launch_bounds__(256, 8): 32-reg cap -> 8 CTAs / 64 warps per SM (100%).

__device__ __forceinline__ float bil(const float* m,
                                     float X0, float Y0, float X1, float Y1) {
    float d0 = fmaf(m[2], Y1, fmaf(m[1], X1, m[0]));
    float d1 = fmaf(m[5], Y1, fmaf(m[4], X1, m[3]));
    float d2 = fmaf(m[8], Y1, fmaf(m[7], X1, m[6]));
    return fmaf(Y0, d2, fmaf(X0, d1, d0));
}

__global__ void __launch_bounds__(256, 8) qcirc_kernel(
    const float4* __restrict__ noise, float4* __restrict__ out,
    const float* __restrict__ qw, int t)
{
    __shared__ float sc[12], ss[12];        // sincos of the 12 half-angles
    __shared__ float sgr[16], sgi[16];      // gate entries (l,w,i,j)
    __shared__ float sWr[16], sWi[16];      // final W (row r, col m)
    __shared__ float sReA[32];              // Re(W^H S W), 2 obs x 16
    __shared__ __align__(16) float sM[20];  // output bilinear forms

    const unsigned FULL = 0xFFFFFFFFu;
    int tid = threadIdx.x;

    if (tid < 32) {
        int lane = tid;

        // Stage 1: 12 sincos in parallel
        if (lane < 12) {
            int l = lane / 6, rem = lane % 6, w = rem / 3, k = rem % 3;
            float phi = qw[l * 6 + w * 3 + 0];
            float th  = qw[l * 6 + w * 3 + 1];
            float om  = qw[l * 6 + w * 3 + 2];
            float ang = (k == 0) ? 0.5f * th
                      : (k == 1) ? 0.5f * (phi + om)
                                 : 0.5f * (phi - om);
            float s, c;
            __sincosf(ang, &s, &c);
            sc[lane] = c; ss[lane] = s;
        }
        __syncwarp(FULL);

        // Stage 2: 16 gate entries in parallel.
        // Rot = RZ(om) RY(th) RZ(phi):
        //  (0,0)=( ct*ca, -ct*sa)  (0,1)=(-st*cb, -st*sb)
        //  (1,0)=( st*cb, -st*sb)  (1,1)=( ct*ca,  ct*sa)
        if (lane < 16) {
            int l = lane >> 3, w = (lane >> 2) & 1, i = (lane >> 1) & 1, j = lane & 1;
            int base = l * 6 + w * 3;
            float ct = sc[base + 0], st = ss[base + 0];
            float ca = sc[base + 1], sa = ss[base + 1];
            float cb = sc[base + 2], sb = ss[base + 2];
            float re = (i == j) ? ct * ca : ((i == 0) ? -st * cb : st * cb);
            float im = (i == 0) ? ((j == 0) ? -ct * sa : -st * sb)
                                : ((j == 0) ? -st * sb :  ct * sa);
            sgr[lane] = re; sgi[lane] = im;
        }
        __syncwarp(FULL);

        // Stage 3: W evolution, one complex entry per lane.
        // q = r*4 + m, r = basis row (i*2+j), m = column. Lanes 16-31 mirror.
        int q = lane & 15;
        int r = q >> 2, m = q & 3;
        int i = r >> 1, j = r & 1;
        // W init = D = diag(1, -i, -i, -1)
        float wr = (q == 0) ? 1.f : ((q == 15) ? -1.f : 0.f);
        float wi = (q == 5 || q == 10) ? -1.f : 0.f;

        #pragma unroll
        for (int l = 0; l < 2; l++) {
            // Gate on qubit 0: new(i,j) = g0[i][0]*W(0,j) + g0[i][1]*W(1,j)
            {
                float ar = __shfl_sync(FULL, wr, j * 4 + m);
                float ai = __shfl_sync(FULL, wi, j * 4 + m);
                float br = __shfl_sync(FULL, wr, (2 + j) * 4 + m);
                float bi = __shfl_sync(FULL, wi, (2 + j) * 4 + m);
                int c0 = (l * 2 + 0) * 4 + i * 2;
                float g0r = sgr[c0],     g0i = sgi[c0];
                float g1r = sgr[c0 + 1], g1i = sgi[c0 + 1];
                wr = g0r * ar - g0i * ai + g1r * br - g1i * bi;
                wi = g0r * ai + g0i * ar + g1r * bi + g1i * br;
            }
            // Gate on qubit 1: new(i,j) = g1[j][0]*W(i,0) + g1[j][1]*W(i,1)
            {
                float ar = __shfl_sync(FULL, wr, (2 * i) * 4 + m);
                float ai = __shfl_sync(FULL, wi, (2 * i) * 4 + m);
                float br = __shfl_sync(FULL, wr, (2 * i + 1) * 4 + m);
                float bi = __shfl_sync(FULL, wi, (2 * i + 1) * 4 + m);
                int c0 = (l * 2 + 1) * 4 + j * 2;
                float g0r = sgr[c0],     g0i = sgi[c0];
                float g1r = sgr[c0 + 1], g1i = sgi[c0 + 1];
                wr = g0r * ar - g0i * ai + g1r * br - g1i * bi;
                wi = g0r * ai + g0i * ar + g1r * bi + g1i * br;
            }
            // Fused CNOT(0->1) then CNOT(1->0): new(i,j) = old(i^j, i)
            {
                int sp = ((i ^ j) * 2 + i) * 4 + m;
                float nwr = __shfl_sync(FULL, wr, sp);
                float nwi = __shfl_sync(FULL, wi, sp);
                wr = nwr; wi = nwi;
            }
        }
        if (lane < 16) { sWr[q] = wr; sWi[q] = wi; }
        __syncwarp(FULL);

        // Stage 4: ReA[j][m] = Re((W^H S W))[j][m], one per lane
        {
            int obs = lane >> 4, jj = (lane >> 2) & 3, mm = lane & 3;
            float acc = 0.f;
            #pragma unroll
            for (int k = 0; k < 4; k++) {
                float sk = (obs == 0) ? ((k < 2) ? 1.f : -1.f)
                                      : ((k & 1) ? -1.f : 1.f);
                acc += sk * (sWr[k * 4 + jj] * sWr[k * 4 + mm]
                           + sWi[k * 4 + jj] * sWi[k * 4 + mm]);
            }
            sReA[lane] = acc;
        }
        __syncwarp(FULL);

        // Stage 5: project onto (1,X,Y) x (1,X,Y), one M entry per lane.
        // Qu sparsity: index e has two (a,b,sign) pairs:
        //  e=0: (0,0,+),(1,1,+)  e=1: (0,0,+),(1,1,-)  e=2: (0,1,+),(1,0,+)
        if (lane < 20) {
            if (lane < 18) {
                const int   A0[3] = {0, 0, 0}, B0[3] = {0, 0, 1};
                const int   A1[3] = {1, 1, 1}, B1[3] = {1, 1, 0};
                const float S1[3] = {1.f, -1.f, 1.f};
                int obs = lane / 9, e = lane % 9, al = e / 3, be = e % 3;
                const float* Rbase = sReA + obs * 16;
                float acc = 0.f;
                #pragma unroll
                for (int p = 0; p < 2; p++) {
                    int ap = p ? A1[al] : A0[al];
                    int bp = p ? B1[al] : B0[al];
                    float sp = p ? S1[al] : 1.f;
                    #pragma unroll
                    for (int qq = 0; qq < 2; qq++) {
                        int aq = qq ? A1[be] : A0[be];
                        int bq = qq ? B1[be] : B0[be];
                        float sq = qq ? S1[be] : 1.f;
                        acc += sp * sq * Rbase[(2 * ap + aq) * 4 + (2 * bp + bq)];
                    }
                }
                sM[lane] = 0.25f * acc;
            } else {
                sM[lane] = 0.f;
            }
        }
    }
    __syncthreads();

    // ---- Hot path: 4 samples/thread, two coalesced float4 streams ---------
    int idx = blockIdx.x * blockDim.x + tid;
    if (idx >= t) return;

    float4 a = noise[idx];
    float4 b = noise[idx + t];

    float M[20];
    const float4* sp4 = reinterpret_cast<const float4*>(sM);
    #pragma unroll
    for (int k = 0; k < 5; k++) {
        float4 v = sp4[k];
        M[4 * k + 0] = v.x; M[4 * k + 1] = v.y;
        M[4 * k + 2] = v.z; M[4 * k + 3] = v.w;
    }

    const float PI = 3.14159265358979323846f;
    float Xa, Ya, Xb, Yb, Xc, Yc, Xd, Yd;
    float4 ra, rb;

    __sincosf(a.x * PI, &Ya, &Xa);
    __sincosf(a.y * PI, &Yb, &Xb);
    __sincosf(a.z * PI, &Yc, &Xc);
    __sincosf(a.w * PI, &Yd, &Xd);
    ra.x = bil(M + 0, Xa, Ya, Xb, Yb);
    ra.y = bil(M + 9, Xa, Ya, Xb, Yb);
    ra.z = bil(M + 0, Xc, Yc, Xd, Yd);
    ra.w = bil(M + 9, Xc, Yc, Xd, Yd);

    __sincosf(b.x * PI, &Ya, &Xa);
    __sincosf(b.y * PI, &Yb, &Xb);
    __sincosf(b.z * PI, &Yc, &Xc);
    __sincosf(b.w * PI, &Yd, &Xd);
    rb.x = bil(M + 0, Xa, Ya, Xb, Yb);
    rb.y = bil(M + 9, Xa, Ya, Xb, Yb);
    rb.z = bil(M + 0, Xc, Yc, Xd, Yd);
    rb.w = bil(M + 9, Xc, Yc, Xd, Yd);

    out[idx] = ra;
    out[idx + t] = rb;
}

extern "C" void kernel_launch(void* const* d_in, const int* in_sizes, int n_in,
                              void* d_out, int out_size) {
    const float* noise = (const float*)d_in[0];     // [B, 2] f32
    const float* qw    = (const float*)d_in[1];     // [2, 2, 3] f32

    int n4 = in_sizes[0] / 4;   // float4 count
    int t = n4 / 2;             // threads; each handles float4 idx and idx+t
    int threads = 256;
    int blocks = (t + threads - 1) / threads;
    qcirc_kernel<<<blocks, threads>>>(
        (const float4*)noise, (float4*)d_out, qw, t);
}